// round 16
// baseline (speedup 1.0000x reference)
#include <cuda_runtime.h>
#include <cuda_bf16.h>
#include <cuda_fp16.h>
#include <cstdint>
#include <math.h>

#define NN 100000      // nodes
#define NE 50000       // edges
#define NZ 1000000     // incidences
#define DH 256
#define NC 40

// ---------------- scratch (device globals; no allocations allowed) ----------
__device__ __align__(16) float g_Xcur[(size_t)NN * DH];   // reused as fp16 for layer-1 out
__device__ __align__(16) __half g_Yh[(size_t)NN * DH];    // post-GEMM fp16
__device__ __align__(16) __half g_Xeh[(size_t)NE * DH];   // edge feat fp16
__device__ float g_att_sum[NN];
__device__ int   g_ecnt[NE];
__device__ int   g_eoff[NE + 1];
__device__ int   g_ncnt[NN];
__device__ int   g_noff[NN + 1];
__device__ int   g_efill[NE];
__device__ int   g_nfill[NN];
__device__ int   g_ev_v[NZ];
__device__ int   g_nv_e[NZ];
__device__ float g_nv_att[NZ];
__device__ int   g_partialE[128];
__device__ int   g_partialN[128];
__device__ __align__(16) __nv_bfloat16 g_W1h[256 * 256];
__device__ __align__(16) __nv_bfloat16 g_W1l[256 * 256];
__device__ __align__(16) __nv_bfloat16 g_W2h[256 * 256];
__device__ __align__(16) __nv_bfloat16 g_W2l[256 * 256];
__device__ __align__(16) __nv_bfloat16 g_W3h[64 * 256];
__device__ __align__(16) __nv_bfloat16 g_W3l[64 * 256];

// ---------------- helpers ----------------------------------------------------
__device__ __forceinline__ uint32_t smem_u32(const void* p) {
    uint32_t a;
    asm("{ .reg .u64 t; cvta.to.shared.u64 t, %1; cvt.u32.u64 %0, t; }" : "=r"(a) : "l"(p));
    return a;
}
#define SWZ64(o) ((uint32_t)(o) ^ ((((uint32_t)(o)) >> 3) & 0x30))

__device__ __forceinline__ void ldmx4(uint32_t* r, uint32_t addr) {
    asm volatile("ldmatrix.sync.aligned.m8n8.x4.shared.b16 {%0,%1,%2,%3}, [%4];"
                 : "=r"(r[0]), "=r"(r[1]), "=r"(r[2]), "=r"(r[3]) : "r"(addr));
}
__device__ __forceinline__ void ldmx2(uint32_t* r, uint32_t addr) {
    asm volatile("ldmatrix.sync.aligned.m8n8.x2.shared.b16 {%0,%1}, [%2];"
                 : "=r"(r[0]), "=r"(r[1]) : "r"(addr));
}
__device__ __forceinline__ void mma_bf16(float* c, const uint32_t* a, const uint32_t* b) {
    asm volatile(
        "mma.sync.aligned.m16n8k16.row.col.f32.bf16.bf16.f32 "
        "{%0,%1,%2,%3}, {%4,%5,%6,%7}, {%8,%9}, {%0,%1,%2,%3};"
        : "+f"(c[0]), "+f"(c[1]), "+f"(c[2]), "+f"(c[3])
        : "r"(a[0]), "r"(a[1]), "r"(a[2]), "r"(a[3]), "r"(b[0]), "r"(b[1]));
}
__device__ __forceinline__ void cpasync16(uint32_t saddr, const void* gptr) {
    asm volatile("cp.async.cg.shared.global [%0], [%1], 16;" :: "r"(saddr), "l"(gptr));
}
__device__ __forceinline__ void acc_h4(float* f, uint4 t) {
    uint32_t w[4] = {t.x, t.y, t.z, t.w};
    #pragma unroll
    for (int q = 0; q < 4; q++) {
        float2 fv = __half22float2(*(__half2*)&w[q]);
        f[2 * q] += fv.x; f[2 * q + 1] += fv.y;
    }
}
__device__ __forceinline__ void fma_h4(float* f, uint4 t, float att) {
    uint32_t w[4] = {t.x, t.y, t.z, t.w};
    #pragma unroll
    for (int q = 0; q < 4; q++) {
        float2 fv = __half22float2(*(__half2*)&w[q]);
        f[2 * q] = fmaf(att, fv.x, f[2 * q]);
        f[2 * q + 1] = fmaf(att, fv.y, f[2 * q + 1]);
    }
}

// ---------------- preprocessing (split E-chain / N-chain) --------------------
__global__ void zeroE_kernel() {
    int i = blockIdx.x * blockDim.x + threadIdx.x;
    int stride = gridDim.x * blockDim.x;
    for (int j = i; j < NE; j += stride) { g_ecnt[j] = 0; g_efill[j] = 0; }
}
__global__ void zeroN_kernel() {
    int i = blockIdx.x * blockDim.x + threadIdx.x;
    int stride = gridDim.x * blockDim.x;
    for (int j = i; j < NN; j += stride) { g_ncnt[j] = 0; g_nfill[j] = 0; g_att_sum[j] = 0.f; }
}

__global__ void histE_kernel(const int* __restrict__ E) {
    int i = blockIdx.x * blockDim.x + threadIdx.x;
    if (i >= NZ) return;
    atomicAdd(&g_ecnt[E[i]], 1);
}
__global__ void histN_kernel(const int* __restrict__ V, const int* __restrict__ E,
                             const float* __restrict__ homo) {
    int i = blockIdx.x * blockDim.x + threadIdx.x;
    if (i >= NZ) return;
    int v = V[i];
    atomicAdd(&g_ncnt[v], 1);
    atomicAdd(&g_att_sum[v], homo[E[i]]);
}

__device__ __forceinline__ int warp_incl_scan(int x, int lane) {
    #pragma unroll
    for (int o = 1; o < 32; o <<= 1) {
        int y = __shfl_up_sync(0xffffffffu, x, o);
        if (lane >= o) x += y;
    }
    return x;
}

__global__ void scan_p1(const int* __restrict__ cnt, int* __restrict__ off, int L,
                        int* __restrict__ partial) {
    __shared__ int wsum[32];
    int t = threadIdx.x, lane = t & 31, w = t >> 5;
    int i = blockIdx.x * 1024 + t;
    int x = (i < L) ? cnt[i] : 0;
    int incl = warp_incl_scan(x, lane);
    if (lane == 31) wsum[w] = incl;
    __syncthreads();
    if (w == 0) wsum[lane] = warp_incl_scan(wsum[lane], lane);
    __syncthreads();
    int blockIncl = incl + (w ? wsum[w - 1] : 0);
    if (i < L) off[i + 1] = blockIncl;
    if (t == 1023) partial[blockIdx.x] = blockIncl;
}

__global__ void scan_p2(int* __restrict__ partial, int nb) {
    __shared__ int wsum[32];
    int t = threadIdx.x, lane = t & 31, w = t >> 5;
    int x = (t < nb) ? partial[t] : 0;
    int incl = warp_incl_scan(x, lane);
    if (lane == 31) wsum[w] = incl;
    __syncthreads();
    if (w == 0) wsum[lane] = warp_incl_scan(wsum[lane], lane);
    __syncthreads();
    int blockIncl = incl + (w ? wsum[w - 1] : 0);
    if (t < nb) partial[t] = blockIncl - x;
}

__global__ void scan_p3(int* __restrict__ off, int L, const int* __restrict__ partial) {
    int i = blockIdx.x * 1024 + threadIdx.x;
    if (i < L) off[i + 1] += partial[blockIdx.x];
    if (i == 0) off[0] = 0;
}

__global__ void buildE_kernel(const int* __restrict__ V, const int* __restrict__ E) {
    int i = blockIdx.x * blockDim.x + threadIdx.x;
    if (i >= NZ) return;
    int e = E[i];
    int p = g_eoff[e] + atomicAdd(&g_efill[e], 1);
    g_ev_v[p] = V[i];
}
__global__ void buildN_kernel(const int* __restrict__ V, const int* __restrict__ E,
                              const float* __restrict__ homo) {
    int i = blockIdx.x * blockDim.x + threadIdx.x;
    if (i >= NZ) return;
    int e = E[i], v = V[i];
    int q = g_noff[v] + atomicAdd(&g_nfill[v], 1);
    g_nv_e[q] = e;
    g_nv_att[q] = homo[e] / g_att_sum[v];
}

// ---------------- fused weight transpose + bf16 split ------------------------
__global__ void wsplit_all(const float* __restrict__ W1, const float* __restrict__ W2,
                           const float* __restrict__ W3) {
    int b = blockIdx.x;
    if (b < 128) {
        const float* W = (b < 64) ? W1 : W2;
        __nv_bfloat16* hi = (b < 64) ? g_W1h : g_W2h;
        __nv_bfloat16* lo = (b < 64) ? g_W1l : g_W2l;
        int i = (b & 63) * 1024 + threadIdx.x;
        int n = i >> 8, k = i & 255;
        float w = W[k * 256 + n];
        __nv_bfloat16 h = __float2bfloat16(w);
        hi[i] = h;
        lo[i] = __float2bfloat16(w - __bfloat162float(h));
    } else {
        int i = (b - 128) * 1024 + threadIdx.x;
        int n = i >> 8, k = i & 255;
        float w = (n < NC) ? W3[k * NC + n] : 0.f;
        __nv_bfloat16 h = __float2bfloat16(w);
        g_W3h[i] = h;
        g_W3l[i] = __float2bfloat16(w - __bfloat162float(h));
    }
}

// ---------------- pipelined split-bf16 tensor GEMM (fp16 output) -------------
template <int BN, bool AHALF>
__global__ void __launch_bounds__(256, 2) gemm_mma(
    const void* __restrict__ Araw,
    const __nv_bfloat16* __restrict__ BHg, const __nv_bfloat16* __restrict__ BLg,
    __half* __restrict__ Ch, int nrows, int ldC, int ncols)
{
    constexpr int NI = BN / 32;
    constexpr uint32_t OFF_AL = 4096;
    constexpr uint32_t OFF_BH = 8192;
    constexpr uint32_t OFF_BL = 8192 + BN * 64;
    constexpr uint32_t STG = 8192 + BN * 128;
    extern __shared__ char sm[];
    uint32_t sb = smem_u32(sm);
    int tid = threadIdx.x, wid = tid >> 5, lane = tid & 31;
    int rowBase = blockIdx.x * 64;
    int wr = (wid >> 2) * 32;
    int wn = (wid & 3) * (BN / 4);

    float acc[2][NI][4];
    #pragma unroll
    for (int mi = 0; mi < 2; mi++)
        #pragma unroll
        for (int ni = 0; ni < NI; ni++)
            #pragma unroll
            for (int q = 0; q < 4; q++) acc[mi][ni][q] = 0.f;

    int aRow = tid >> 2, aSeg = tid & 3;
    bool aValid = (rowBase + aRow) < nrows;
    size_t aOff = (size_t)(rowBase + aRow) * 256 + aSeg * 8;
    uint32_t aStoreSw = SWZ64(aRow * 64 + aSeg * 16);

    int am = lane >> 3;
    int arow = ((am & 1) << 3) + (lane & 7);
    int akb = (am >> 1) << 4;
    int bt = lane & 15;
    int brow = bt & 7;
    int bkb = (bt >> 3) << 4;

    float eReg[8];

    auto loadA = [&](int k0) {
        if (!AHALF) {
            float4 f0 = {0, 0, 0, 0}, f1 = {0, 0, 0, 0};
            if (aValid) {
                const float4* p = (const float4*)((const float*)Araw + aOff + k0);
                f0 = p[0]; f1 = p[1];
            }
            eReg[0] = f0.x; eReg[1] = f0.y; eReg[2] = f0.z; eReg[3] = f0.w;
            eReg[4] = f1.x; eReg[5] = f1.y; eReg[6] = f1.z; eReg[7] = f1.w;
        } else {
            uint4 t = {0, 0, 0, 0};
            if (aValid)
                t = *(const uint4*)((const __half*)Araw + aOff + k0);
            uint32_t w[4] = {t.x, t.y, t.z, t.w};
            #pragma unroll
            for (int q = 0; q < 4; q++) {
                float2 fv = __half22float2(*(__half2*)&w[q]);
                eReg[2 * q] = fv.x; eReg[2 * q + 1] = fv.y;
            }
        }
    };
    auto storeA = [&](uint32_t stg) {
        uint32_t hv[4], lv[4];
        #pragma unroll
        for (int q = 0; q < 4; q++) {
            float a = eReg[2 * q], b = eReg[2 * q + 1];
            __nv_bfloat16 ha = __float2bfloat16(a), hb = __float2bfloat16(b);
            __nv_bfloat162 hp; hp.x = ha; hp.y = hb;
            hv[q] = *(uint32_t*)&hp;
            __nv_bfloat162 lp;
            lp.x = __float2bfloat16(a - __bfloat162float(ha));
            lp.y = __float2bfloat16(b - __bfloat162float(hb));
            lv[q] = *(uint32_t*)&lp;
        }
        *(uint4*)(sm + stg + aStoreSw) = make_uint4(hv[0], hv[1], hv[2], hv[3]);
        *(uint4*)(sm + stg + OFF_AL + aStoreSw) = make_uint4(lv[0], lv[1], lv[2], lv[3]);
    };
    auto loadB = [&](uint32_t stg, int k0) {
        #pragma unroll
        for (int g = 0; g < BN / 64; g++) {
            int gi = tid + g * 256;
            int row = gi >> 2, cp = gi & 3;
            uint32_t sw = SWZ64(row * 64 + cp * 16);
            size_t src = (size_t)row * 256 + k0 + cp * 8;
            cpasync16(sb + stg + OFF_BH + sw, BHg + src);
            cpasync16(sb + stg + OFF_BL + sw, BLg + src);
        }
        asm volatile("cp.async.commit_group;" ::: "memory");
    };
    auto compute = [&](uint32_t stg) {
        #pragma unroll
        for (int s = 0; s < 2; s++) {
            uint32_t ah[2][4], al[2][4];
            #pragma unroll
            for (int mi = 0; mi < 2; mi++) {
                uint32_t off = SWZ64((wr + mi * 16 + arow) * 64 + s * 32 + akb);
                ldmx4(ah[mi], sb + stg + off);
                ldmx4(al[mi], sb + stg + OFF_AL + off);
            }
            #pragma unroll
            for (int ni = 0; ni < NI; ni++) {
                uint32_t off = SWZ64((wn + ni * 8 + brow) * 64 + s * 32 + bkb);
                uint32_t bh[2], bl[2];
                ldmx2(bh, sb + stg + OFF_BH + off);
                ldmx2(bl, sb + stg + OFF_BL + off);
                #pragma unroll
                for (int mi = 0; mi < 2; mi++) {
                    mma_bf16(acc[mi][ni], ah[mi], bh);
                    mma_bf16(acc[mi][ni], ah[mi], bl);
                    mma_bf16(acc[mi][ni], al[mi], bh);
                }
            }
        }
    };

    loadA(0);
    loadB(0, 0);
    storeA(0);
    asm volatile("cp.async.wait_group 0;" ::: "memory");
    __syncthreads();

    uint32_t buf = 0;
    #pragma unroll
    for (int c = 0; c < 8; c++) {
        uint32_t cur = buf * STG, nxt = (buf ^ 1) * STG;
        if (c < 7) {
            loadA((c + 1) * 32);
            loadB(nxt, (c + 1) * 32);
        }
        compute(cur);
        if (c < 7) {
            storeA(nxt);
            asm volatile("cp.async.wait_group 0;" ::: "memory");
            __syncthreads();
        }
        buf ^= 1;
    }

    int g = lane >> 2, tig = lane & 3;
    #pragma unroll
    for (int mi = 0; mi < 2; mi++) {
        int r0 = rowBase + wr + mi * 16 + g;
        int r1 = r0 + 8;
        #pragma unroll
        for (int ni = 0; ni < NI; ni++) {
            int col = wn + ni * 8 + 2 * tig;
            if (col < ncols) {
                if (r0 < nrows)
                    *(__half2*)(Ch + (size_t)r0 * ldC + col) =
                        __floats2half2_rn(acc[mi][ni][0], acc[mi][ni][1]);
                if (r1 < nrows)
                    *(__half2*)(Ch + (size_t)r1 * ldC + col) =
                        __floats2half2_rn(acc[mi][ni][2], acc[mi][ni][3]);
            }
        }
    }
}

// ---------------- edge aggregation: fp16 gather (__ldg), fp32 accum ----------
template <int D>
__global__ void edge_agg_kernel(const __half* __restrict__ Yh, __half* __restrict__ Xeh) {
    int warpId = (blockIdx.x * blockDim.x + threadIdx.x) >> 5;
    int lane = threadIdx.x & 31;
    if (warpId >= NE) return;
    int beg = g_eoff[warpId], end = g_eoff[warpId + 1];
    if (D == 256) {
        float f[8];
        #pragma unroll
        for (int q = 0; q < 8; q++) f[q] = 0.f;
        int p = beg;
        for (; p + 7 < end; p += 8) {
            uint4 t[8];
            #pragma unroll
            for (int j = 0; j < 8; j++) {
                int v = g_ev_v[p + j];
                t[j] = __ldg(((const uint4*)(Yh + (size_t)v * D)) + lane);
            }
            #pragma unroll
            for (int j = 0; j < 8; j++) acc_h4(f, t[j]);
        }
        for (; p + 3 < end; p += 4) {
            uint4 t[4];
            #pragma unroll
            for (int j = 0; j < 4; j++) {
                int v = g_ev_v[p + j];
                t[j] = __ldg(((const uint4*)(Yh + (size_t)v * D)) + lane);
            }
            #pragma unroll
            for (int j = 0; j < 4; j++) acc_h4(f, t[j]);
        }
        for (; p < end; p++) {
            int v = g_ev_v[p];
            acc_h4(f, __ldg(((const uint4*)(Yh + (size_t)v * D)) + lane));
        }
        int cnt = end - beg;
        float s = 1.f / (float)(cnt > 0 ? cnt : 1);
        uint32_t o[4];
        #pragma unroll
        for (int q = 0; q < 4; q++) {
            __half2 h = __floats2half2_rn(f[2 * q] * s, f[2 * q + 1] * s);
            o[q] = *(uint32_t*)&h;
        }
        ((uint4*)(Xeh + (size_t)warpId * D))[lane] = make_uint4(o[0], o[1], o[2], o[3]);
    } else {
        float f0 = 0.f, f1 = 0.f;
        bool act = lane < D / 2;
        int p = beg;
        for (; p + 3 < end; p += 4) {
            int v0 = g_ev_v[p], v1 = g_ev_v[p + 1], v2 = g_ev_v[p + 2], v3 = g_ev_v[p + 3];
            if (act) {
                uint32_t w0 = __ldg(((const uint32_t*)(Yh + (size_t)v0 * D)) + lane);
                uint32_t w1 = __ldg(((const uint32_t*)(Yh + (size_t)v1 * D)) + lane);
                uint32_t w2 = __ldg(((const uint32_t*)(Yh + (size_t)v2 * D)) + lane);
                uint32_t w3 = __ldg(((const uint32_t*)(Yh + (size_t)v3 * D)) + lane);
                float2 a = __half22float2(*(__half2*)&w0);
                float2 b = __half22float2(*(__half2*)&w1);
                float2 c = __half22float2(*(__half2*)&w2);
                float2 d = __half22float2(*(__half2*)&w3);
                f0 += a.x + b.x + c.x + d.x;
                f1 += a.y + b.y + c.y + d.y;
            }
        }
        for (; p < end; p++) {
            int v = g_ev_v[p];
            if (act) {
                uint32_t t = __ldg(((const uint32_t*)(Yh + (size_t)v * D)) + lane);
                float2 fv = __half22float2(*(__half2*)&t);
                f0 += fv.x; f1 += fv.y;
            }
        }
        int cnt = end - beg;
        float s = 1.f / (float)(cnt > 0 ? cnt : 1);
        if (act) {
            __half2 h = __floats2half2_rn(f0 * s, f1 * s);
            ((uint32_t*)(Xeh + (size_t)warpId * D))[lane] = *(uint32_t*)&h;
        }
    }
}

// ---------------- node aggregation + residual + L2 norm (+relu) -------------
template <int D, bool RELU, bool OUT_HALF>
__global__ void node_agg_kernel(const __half* __restrict__ Yh, const __half* __restrict__ Xeh,
                                void* __restrict__ Xout) {
    int warpId = (blockIdx.x * blockDim.x + threadIdx.x) >> 5;
    int lane = threadIdx.x & 31;
    if (warpId >= NN) return;
    int beg = g_noff[warpId], end = g_noff[warpId + 1];
    if (D == 256) {
        float f[8];
        {
            uint4 y = ((const uint4*)(Yh + (size_t)warpId * D))[lane];
            uint32_t w[4] = {y.x, y.y, y.z, y.w};
            #pragma unroll
            for (int q = 0; q < 4; q++) {
                float2 fv = __half22float2(*(__half2*)&w[q]);
                f[2 * q] = fv.x; f[2 * q + 1] = fv.y;
            }
        }
        int p = beg;
        for (; p + 3 < end; p += 4) {
            int e0 = g_nv_e[p], e1 = g_nv_e[p + 1], e2 = g_nv_e[p + 2], e3 = g_nv_e[p + 3];
            float a0 = g_nv_att[p], a1 = g_nv_att[p + 1], a2 = g_nv_att[p + 2], a3 = g_nv_att[p + 3];
            uint4 t0 = __ldg(((const uint4*)(Xeh + (size_t)e0 * D)) + lane);
            uint4 t1 = __ldg(((const uint4*)(Xeh + (size_t)e1 * D)) + lane);
            uint4 t2 = __ldg(((const uint4*)(Xeh + (size_t)e2 * D)) + lane);
            uint4 t3 = __ldg(((const uint4*)(Xeh + (size_t)e3 * D)) + lane);
            fma_h4(f, t0, a0); fma_h4(f, t1, a1); fma_h4(f, t2, a2); fma_h4(f, t3, a3);
        }
        for (; p < end; p++) {
            int e = g_nv_e[p];
            fma_h4(f, __ldg(((const uint4*)(Xeh + (size_t)e * D)) + lane), g_nv_att[p]);
        }
        float ss = 0.f;
        #pragma unroll
        for (int q = 0; q < 8; q++) ss += f[q] * f[q];
        #pragma unroll
        for (int o = 16; o; o >>= 1) ss += __shfl_xor_sync(0xffffffffu, ss, o);
        float norm = sqrtf(ss);
        float scale = (norm > 0.f) ? (1.f / norm) : 0.f;
        #pragma unroll
        for (int q = 0; q < 8; q++) {
            f[q] *= scale;
            if (RELU) f[q] = fmaxf(f[q], 0.f);
        }
        if (OUT_HALF) {
            uint32_t o[4];
            #pragma unroll
            for (int q = 0; q < 4; q++) {
                __half2 h = __floats2half2_rn(f[2 * q], f[2 * q + 1]);
                o[q] = *(uint32_t*)&h;
            }
            ((uint4*)((__half*)Xout + (size_t)warpId * D))[lane] = make_uint4(o[0], o[1], o[2], o[3]);
        } else {
            float4* o4 = (float4*)((float*)Xout + (size_t)warpId * D);
            o4[2 * lane] = make_float4(f[0], f[1], f[2], f[3]);
            o4[2 * lane + 1] = make_float4(f[4], f[5], f[6], f[7]);
        }
    } else {
        bool act = lane < D / 2;
        float f0 = 0.f, f1 = 0.f;
        if (act) {
            uint32_t y = ((const uint32_t*)(Yh + (size_t)warpId * D))[lane];
            float2 fv = __half22float2(*(__half2*)&y);
            f0 = fv.x; f1 = fv.y;
        }
        int p = beg;
        for (; p + 3 < end; p += 4) {
            int e0 = g_nv_e[p], e1 = g_nv_e[p + 1], e2 = g_nv_e[p + 2], e3 = g_nv_e[p + 3];
            float a0 = g_nv_att[p], a1 = g_nv_att[p + 1], a2 = g_nv_att[p + 2], a3 = g_nv_att[p + 3];
            if (act) {
                uint32_t w0 = __ldg(((const uint32_t*)(Xeh + (size_t)e0 * D)) + lane);
                uint32_t w1 = __ldg(((const uint32_t*)(Xeh + (size_t)e1 * D)) + lane);
                uint32_t w2 = __ldg(((const uint32_t*)(Xeh + (size_t)e2 * D)) + lane);
                uint32_t w3 = __ldg(((const uint32_t*)(Xeh + (size_t)e3 * D)) + lane);
                float2 a = __half22float2(*(__half2*)&w0);
                float2 b = __half22float2(*(__half2*)&w1);
                float2 c = __half22float2(*(__half2*)&w2);
                float2 d = __half22float2(*(__half2*)&w3);
                f0 = fmaf(a0, a.x, fmaf(a1, b.x, fmaf(a2, c.x, fmaf(a3, d.x, f0))));
                f1 = fmaf(a0, a.y, fmaf(a1, b.y, fmaf(a2, c.y, fmaf(a3, d.y, f1))));
            }
        }
        for (; p < end; p++) {
            int e = g_nv_e[p];
            float att = g_nv_att[p];
            if (act) {
                uint32_t t = __ldg(((const uint32_t*)(Xeh + (size_t)e * D)) + lane);
                float2 fv = __half22float2(*(__half2*)&t);
                f0 = fmaf(att, fv.x, f0);
                f1 = fmaf(att, fv.y, f1);
            }
        }
        float ss = f0 * f0 + f1 * f1;
        #pragma unroll
        for (int o = 16; o; o >>= 1) ss += __shfl_xor_sync(0xffffffffu, ss, o);
        float norm = sqrtf(ss);
        float scale = (norm > 0.f) ? (1.f / norm) : 0.f;
        f0 *= scale; f1 *= scale;
        if (RELU) { f0 = fmaxf(f0, 0.f); f1 = fmaxf(f1, 0.f); }
        if (act)
            ((float2*)((float*)Xout + (size_t)warpId * D))[lane] = make_float2(f0, f1);
    }
}

// ---------------- launch -----------------------------------------------------
extern "C" void kernel_launch(void* const* d_in, const int* in_sizes, int n_in,
                              void* d_out, int out_size) {
    const float* X    = (const float*)d_in[0];
    const int*   V    = (const int*)d_in[1];
    const int*   E    = (const int*)d_in[2];
    const float* homo = (const float*)d_in[3];
    const float* W1   = (const float*)d_in[4];
    const float* W2   = (const float*)d_in[5];
    const float* Wout = (const float*)d_in[6];
    float* out = (float*)d_out;

    float *pXcur;
    __half *pYh, *pXeh;
    int *pEcnt, *pEoff, *pNcnt, *pNoff, *pPartE, *pPartN;
    __nv_bfloat16 *pW1h, *pW1l, *pW2h, *pW2l, *pW3h, *pW3l;
    cudaGetSymbolAddress((void**)&pXcur, g_Xcur);
    cudaGetSymbolAddress((void**)&pYh, g_Yh);
    cudaGetSymbolAddress((void**)&pXeh, g_Xeh);
    cudaGetSymbolAddress((void**)&pEcnt, g_ecnt);
    cudaGetSymbolAddress((void**)&pEoff, g_eoff);
    cudaGetSymbolAddress((void**)&pNcnt, g_ncnt);
    cudaGetSymbolAddress((void**)&pNoff, g_noff);
    cudaGetSymbolAddress((void**)&pPartE, g_partialE);
    cudaGetSymbolAddress((void**)&pPartN, g_partialN);
    cudaGetSymbolAddress((void**)&pW1h, g_W1h);
    cudaGetSymbolAddress((void**)&pW1l, g_W1l);
    cudaGetSymbolAddress((void**)&pW2h, g_W2h);
    cudaGetSymbolAddress((void**)&pW2l, g_W2l);
    cudaGetSymbolAddress((void**)&pW3h, g_W3h);
    cudaGetSymbolAddress((void**)&pW3l, g_W3l);
    __half* pXcurH = (__half*)pXcur;

    const int SMEM_BIG = 2 * (8192 + 256 * 128);   // 81920
    const int SMEM_SML = 2 * (8192 + 64 * 128);    // 32768

    // One-time resource setup (first call = non-captured correctness run).
    static cudaStream_t sE = nullptr, sN = nullptr;
    static cudaEvent_t evFork = nullptr, evJoinE = nullptr, evJoinN = nullptr;
    if (sE == nullptr) {
        cudaStreamCreateWithFlags(&sE, cudaStreamNonBlocking);
        cudaStreamCreateWithFlags(&sN, cudaStreamNonBlocking);
        cudaEventCreateWithFlags(&evFork, cudaEventDisableTiming);
        cudaEventCreateWithFlags(&evJoinE, cudaEventDisableTiming);
        cudaEventCreateWithFlags(&evJoinN, cudaEventDisableTiming);
        cudaFuncSetAttribute(gemm_mma<256, false>, cudaFuncAttributeMaxDynamicSharedMemorySize, SMEM_BIG);
        cudaFuncSetAttribute(gemm_mma<256, true>, cudaFuncAttributeMaxDynamicSharedMemorySize, SMEM_BIG);
        cudaFuncSetAttribute(gemm_mma<64, false>, cudaFuncAttributeMaxDynamicSharedMemorySize, SMEM_SML);
    }

    int nbE = (NE + 1023) / 1024, nbN = (NN + 1023) / 1024;

    // fork: E-chain and N-chain run concurrently with wsplit + layer-1 GEMM
    cudaEventRecord(evFork, 0);
    cudaStreamWaitEvent(sE, evFork, 0);
    cudaStreamWaitEvent(sN, evFork, 0);

    // E-chain (stream sE): edge CSR only
    zeroE_kernel<<<128, 512, 0, sE>>>();
    histE_kernel<<<(NZ + 255) / 256, 256, 0, sE>>>(E);
    scan_p1<<<nbE, 1024, 0, sE>>>(pEcnt, pEoff, NE, pPartE);
    scan_p2<<<1, 1024, 0, sE>>>(pPartE, nbE);
    scan_p3<<<nbE, 1024, 0, sE>>>(pEoff, NE, pPartE);
    buildE_kernel<<<(NZ + 255) / 256, 256, 0, sE>>>(V, E);
    cudaEventRecord(evJoinE, sE);

    // N-chain (stream sN): node CSR + att weights
    zeroN_kernel<<<128, 512, 0, sN>>>();
    histN_kernel<<<(NZ + 255) / 256, 256, 0, sN>>>(V, E, homo);
    scan_p1<<<nbN, 1024, 0, sN>>>(pNcnt, pNoff, NN, pPartN);
    scan_p2<<<1, 1024, 0, sN>>>(pPartN, nbN);
    scan_p3<<<nbN, 1024, 0, sN>>>(pNoff, NN, pPartN);
    buildN_kernel<<<(NZ + 255) / 256, 256, 0, sN>>>(V, E, homo);
    cudaEventRecord(evJoinN, sN);

    const int gemmGrid = (NN + 63) / 64;
    const int eagBlocks = (NE * 32 + 255) / 256;
    const int nagBlocks = (NN * 32 + 255) / 256;

    // GEMM branch (default stream)
    wsplit_all<<<144, 1024>>>(W1, W2, Wout);
    gemm_mma<256, false><<<gemmGrid, 256, SMEM_BIG>>>(X, pW1h, pW1l, pYh, NN, 256, 256);

    // layer 1: edge agg needs only E-CSR; node agg additionally needs N-CSR
    cudaStreamWaitEvent(0, evJoinE, 0);
    edge_agg_kernel<256><<<eagBlocks, 256>>>(pYh, pXeh);
    cudaStreamWaitEvent(0, evJoinN, 0);
    node_agg_kernel<256, true, true><<<nagBlocks, 256>>>(pYh, pXeh, pXcurH);

    // layer 2 (A fp16) -> Z written directly to out (fp32)
    gemm_mma<256, true><<<gemmGrid, 256, SMEM_BIG>>>(pXcurH, pW2h, pW2l, pYh, NN, 256, 256);
    edge_agg_kernel<256><<<eagBlocks, 256>>>(pYh, pXeh);
    node_agg_kernel<256, true, false><<<nagBlocks, 256>>>(pYh, pXeh, out);

    // layer 3 (A fp32 from out; N padded to 64, C stride 40)
    gemm_mma<64, false><<<gemmGrid, 256, SMEM_SML>>>(out, pW3h, pW3l, pYh, NN, NC, NC);
    edge_agg_kernel<NC><<<eagBlocks, 256>>>(pYh, pXeh);
    node_agg_kernel<NC, false, false><<<nagBlocks, 256>>>(pYh, pXeh, out + (size_t)NN * DH);
}

// round 17
// speedup vs baseline: 1.4716x; 1.4716x over previous
#include <cuda_runtime.h>
#include <cuda_bf16.h>
#include <cuda_fp16.h>
#include <cstdint>
#include <math.h>

#define NN 100000      // nodes
#define NE 50000       // edges
#define NZ 1000000     // incidences
#define DH 256
#define NC 40

// ---------------- scratch (device globals; no allocations allowed) ----------
__device__ __align__(16) float g_Xcur[(size_t)NN * DH];   // reused as fp16 for layer-1 out
__device__ __align__(16) __half g_Yh[(size_t)NN * DH];    // post-GEMM fp16
__device__ __align__(16) __half g_Xeh[(size_t)NE * DH];   // edge feat fp16
__device__ float g_att_sum[NN];
__device__ int   g_ecnt[NE];
__device__ int   g_eoff[NE + 1];
__device__ int   g_ncnt[NN];
__device__ int   g_noff[NN + 1];
__device__ int   g_efill[NE];
__device__ int   g_nfill[NN];
__device__ int   g_ev_v[NZ];
__device__ int   g_nv_e[NZ];
__device__ float g_nv_att[NZ];
__device__ int   g_partialE[128];
__device__ int   g_partialN[128];
__device__ __align__(16) __nv_bfloat16 g_W1h[256 * 256];
__device__ __align__(16) __nv_bfloat16 g_W1l[256 * 256];
__device__ __align__(16) __nv_bfloat16 g_W2h[256 * 256];
__device__ __align__(16) __nv_bfloat16 g_W2l[256 * 256];
__device__ __align__(16) __nv_bfloat16 g_W3h[64 * 256];
__device__ __align__(16) __nv_bfloat16 g_W3l[64 * 256];

// ---------------- helpers ----------------------------------------------------
__device__ __forceinline__ uint32_t smem_u32(const void* p) {
    uint32_t a;
    asm("{ .reg .u64 t; cvta.to.shared.u64 t, %1; cvt.u32.u64 %0, t; }" : "=r"(a) : "l"(p));
    return a;
}
#define SWZ64(o) ((uint32_t)(o) ^ ((((uint32_t)(o)) >> 3) & 0x30))

__device__ __forceinline__ void ldmx4(uint32_t* r, uint32_t addr) {
    asm volatile("ldmatrix.sync.aligned.m8n8.x4.shared.b16 {%0,%1,%2,%3}, [%4];"
                 : "=r"(r[0]), "=r"(r[1]), "=r"(r[2]), "=r"(r[3]) : "r"(addr));
}
__device__ __forceinline__ void ldmx2(uint32_t* r, uint32_t addr) {
    asm volatile("ldmatrix.sync.aligned.m8n8.x2.shared.b16 {%0,%1}, [%2];"
                 : "=r"(r[0]), "=r"(r[1]) : "r"(addr));
}
__device__ __forceinline__ void mma_bf16(float* c, const uint32_t* a, const uint32_t* b) {
    asm volatile(
        "mma.sync.aligned.m16n8k16.row.col.f32.bf16.bf16.f32 "
        "{%0,%1,%2,%3}, {%4,%5,%6,%7}, {%8,%9}, {%0,%1,%2,%3};"
        : "+f"(c[0]), "+f"(c[1]), "+f"(c[2]), "+f"(c[3])
        : "r"(a[0]), "r"(a[1]), "r"(a[2]), "r"(a[3]), "r"(b[0]), "r"(b[1]));
}
__device__ __forceinline__ void cpasync16(uint32_t saddr, const void* gptr) {
    asm volatile("cp.async.cg.shared.global [%0], [%1], 16;" :: "r"(saddr), "l"(gptr));
}
__device__ __forceinline__ void acc_h4(float* f, uint4 t) {
    uint32_t w[4] = {t.x, t.y, t.z, t.w};
    #pragma unroll
    for (int q = 0; q < 4; q++) {
        float2 fv = __half22float2(*(__half2*)&w[q]);
        f[2 * q] += fv.x; f[2 * q + 1] += fv.y;
    }
}
__device__ __forceinline__ void fma_h4(float* f, uint4 t, float att) {
    uint32_t w[4] = {t.x, t.y, t.z, t.w};
    #pragma unroll
    for (int q = 0; q < 4; q++) {
        float2 fv = __half22float2(*(__half2*)&w[q]);
        f[2 * q] = fmaf(att, fv.x, f[2 * q]);
        f[2 * q + 1] = fmaf(att, fv.y, f[2 * q + 1]);
    }
}

// ---------------- preprocessing (split E-chain / N-chain) --------------------
__global__ void zeroE_kernel() {
    int i = blockIdx.x * blockDim.x + threadIdx.x;
    int stride = gridDim.x * blockDim.x;
    for (int j = i; j < NE; j += stride) { g_ecnt[j] = 0; g_efill[j] = 0; }
}
__global__ void zeroN_kernel() {
    int i = blockIdx.x * blockDim.x + threadIdx.x;
    int stride = gridDim.x * blockDim.x;
    for (int j = i; j < NN; j += stride) { g_ncnt[j] = 0; g_nfill[j] = 0; g_att_sum[j] = 0.f; }
}

__global__ void histE_kernel(const int* __restrict__ E) {
    int i = blockIdx.x * blockDim.x + threadIdx.x;
    if (i >= NZ) return;
    atomicAdd(&g_ecnt[E[i]], 1);
}
__global__ void histN_kernel(const int* __restrict__ V, const int* __restrict__ E,
                             const float* __restrict__ homo) {
    int i = blockIdx.x * blockDim.x + threadIdx.x;
    if (i >= NZ) return;
    int v = V[i];
    atomicAdd(&g_ncnt[v], 1);
    atomicAdd(&g_att_sum[v], homo[E[i]]);
}

__device__ __forceinline__ int warp_incl_scan(int x, int lane) {
    #pragma unroll
    for (int o = 1; o < 32; o <<= 1) {
        int y = __shfl_up_sync(0xffffffffu, x, o);
        if (lane >= o) x += y;
    }
    return x;
}

__global__ void scan_p1(const int* __restrict__ cnt, int* __restrict__ off, int L,
                        int* __restrict__ partial) {
    __shared__ int wsum[32];
    int t = threadIdx.x, lane = t & 31, w = t >> 5;
    int i = blockIdx.x * 1024 + t;
    int x = (i < L) ? cnt[i] : 0;
    int incl = warp_incl_scan(x, lane);
    if (lane == 31) wsum[w] = incl;
    __syncthreads();
    if (w == 0) wsum[lane] = warp_incl_scan(wsum[lane], lane);
    __syncthreads();
    int blockIncl = incl + (w ? wsum[w - 1] : 0);
    if (i < L) off[i + 1] = blockIncl;
    if (t == 1023) partial[blockIdx.x] = blockIncl;
}

__global__ void scan_p2(int* __restrict__ partial, int nb) {
    __shared__ int wsum[32];
    int t = threadIdx.x, lane = t & 31, w = t >> 5;
    int x = (t < nb) ? partial[t] : 0;
    int incl = warp_incl_scan(x, lane);
    if (lane == 31) wsum[w] = incl;
    __syncthreads();
    if (w == 0) wsum[lane] = warp_incl_scan(wsum[lane], lane);
    __syncthreads();
    int blockIncl = incl + (w ? wsum[w - 1] : 0);
    if (t < nb) partial[t] = blockIncl - x;
}

__global__ void scan_p3(int* __restrict__ off, int L, const int* __restrict__ partial) {
    int i = blockIdx.x * 1024 + threadIdx.x;
    if (i < L) off[i + 1] += partial[blockIdx.x];
    if (i == 0) off[0] = 0;
}

__global__ void buildE_kernel(const int* __restrict__ V, const int* __restrict__ E) {
    int i = blockIdx.x * blockDim.x + threadIdx.x;
    if (i >= NZ) return;
    int e = E[i];
    int p = g_eoff[e] + atomicAdd(&g_efill[e], 1);
    g_ev_v[p] = V[i];
}
__global__ void buildN_kernel(const int* __restrict__ V, const int* __restrict__ E,
                              const float* __restrict__ homo) {
    int i = blockIdx.x * blockDim.x + threadIdx.x;
    if (i >= NZ) return;
    int e = E[i], v = V[i];
    int q = g_noff[v] + atomicAdd(&g_nfill[v], 1);
    g_nv_e[q] = e;
    g_nv_att[q] = homo[e] / g_att_sum[v];
}

// ---------------- fused weight transpose + bf16 split ------------------------
__global__ void wsplit_all(const float* __restrict__ W1, const float* __restrict__ W2,
                           const float* __restrict__ W3) {
    int b = blockIdx.x;
    if (b < 128) {
        const float* W = (b < 64) ? W1 : W2;
        __nv_bfloat16* hi = (b < 64) ? g_W1h : g_W2h;
        __nv_bfloat16* lo = (b < 64) ? g_W1l : g_W2l;
        int i = (b & 63) * 1024 + threadIdx.x;
        int n = i >> 8, k = i & 255;
        float w = W[k * 256 + n];
        __nv_bfloat16 h = __float2bfloat16(w);
        hi[i] = h;
        lo[i] = __float2bfloat16(w - __bfloat162float(h));
    } else {
        int i = (b - 128) * 1024 + threadIdx.x;
        int n = i >> 8, k = i & 255;
        float w = (n < NC) ? W3[k * NC + n] : 0.f;
        __nv_bfloat16 h = __float2bfloat16(w);
        g_W3h[i] = h;
        g_W3l[i] = __float2bfloat16(w - __bfloat162float(h));
    }
}

// ---------------- pipelined split-bf16 tensor GEMM (fp16 output) -------------
// AHALF: A is fp16 (layer-2 reads fp16 Xcur); else fp32.
template <int BN, bool AHALF>
__global__ void __launch_bounds__(256, 2) gemm_mma(
    const void* __restrict__ Araw,
    const __nv_bfloat16* __restrict__ BHg, const __nv_bfloat16* __restrict__ BLg,
    __half* __restrict__ Ch, int nrows, int ldC, int ncols)
{
    constexpr int NI = BN / 32;
    constexpr uint32_t OFF_AL = 4096;
    constexpr uint32_t OFF_BH = 8192;
    constexpr uint32_t OFF_BL = 8192 + BN * 64;
    constexpr uint32_t STG = 8192 + BN * 128;
    extern __shared__ char sm[];
    uint32_t sb = smem_u32(sm);
    int tid = threadIdx.x, wid = tid >> 5, lane = tid & 31;
    int rowBase = blockIdx.x * 64;
    int wr = (wid >> 2) * 32;
    int wn = (wid & 3) * (BN / 4);

    float acc[2][NI][4];
    #pragma unroll
    for (int mi = 0; mi < 2; mi++)
        #pragma unroll
        for (int ni = 0; ni < NI; ni++)
            #pragma unroll
            for (int q = 0; q < 4; q++) acc[mi][ni][q] = 0.f;

    int aRow = tid >> 2, aSeg = tid & 3;
    bool aValid = (rowBase + aRow) < nrows;
    size_t aOff = (size_t)(rowBase + aRow) * 256 + aSeg * 8;
    uint32_t aStoreSw = SWZ64(aRow * 64 + aSeg * 16);

    int am = lane >> 3;
    int arow = ((am & 1) << 3) + (lane & 7);
    int akb = (am >> 1) << 4;
    int bt = lane & 15;
    int brow = bt & 7;
    int bkb = (bt >> 3) << 4;

    float eReg[8];

    auto loadA = [&](int k0) {
        if (!AHALF) {
            float4 f0 = {0, 0, 0, 0}, f1 = {0, 0, 0, 0};
            if (aValid) {
                const float4* p = (const float4*)((const float*)Araw + aOff + k0);
                f0 = p[0]; f1 = p[1];
            }
            eReg[0] = f0.x; eReg[1] = f0.y; eReg[2] = f0.z; eReg[3] = f0.w;
            eReg[4] = f1.x; eReg[5] = f1.y; eReg[6] = f1.z; eReg[7] = f1.w;
        } else {
            uint4 t = {0, 0, 0, 0};
            if (aValid)
                t = *(const uint4*)((const __half*)Araw + aOff + k0);
            uint32_t w[4] = {t.x, t.y, t.z, t.w};
            #pragma unroll
            for (int q = 0; q < 4; q++) {
                float2 fv = __half22float2(*(__half2*)&w[q]);
                eReg[2 * q] = fv.x; eReg[2 * q + 1] = fv.y;
            }
        }
    };
    auto storeA = [&](uint32_t stg) {
        uint32_t hv[4], lv[4];
        #pragma unroll
        for (int q = 0; q < 4; q++) {
            float a = eReg[2 * q], b = eReg[2 * q + 1];
            __nv_bfloat16 ha = __float2bfloat16(a), hb = __float2bfloat16(b);
            __nv_bfloat162 hp; hp.x = ha; hp.y = hb;
            hv[q] = *(uint32_t*)&hp;
            __nv_bfloat162 lp;
            lp.x = __float2bfloat16(a - __bfloat162float(ha));
            lp.y = __float2bfloat16(b - __bfloat162float(hb));
            lv[q] = *(uint32_t*)&lp;
        }
        *(uint4*)(sm + stg + aStoreSw) = make_uint4(hv[0], hv[1], hv[2], hv[3]);
        *(uint4*)(sm + stg + OFF_AL + aStoreSw) = make_uint4(lv[0], lv[1], lv[2], lv[3]);
    };
    auto loadB = [&](uint32_t stg, int k0) {
        #pragma unroll
        for (int g = 0; g < BN / 64; g++) {
            int gi = tid + g * 256;
            int row = gi >> 2, cp = gi & 3;
            uint32_t sw = SWZ64(row * 64 + cp * 16);
            size_t src = (size_t)row * 256 + k0 + cp * 8;
            cpasync16(sb + stg + OFF_BH + sw, BHg + src);
            cpasync16(sb + stg + OFF_BL + sw, BLg + src);
        }
        asm volatile("cp.async.commit_group;" ::: "memory");
    };
    auto compute = [&](uint32_t stg) {
        #pragma unroll
        for (int s = 0; s < 2; s++) {
            uint32_t ah[2][4], al[2][4];
            #pragma unroll
            for (int mi = 0; mi < 2; mi++) {
                uint32_t off = SWZ64((wr + mi * 16 + arow) * 64 + s * 32 + akb);
                ldmx4(ah[mi], sb + stg + off);
                ldmx4(al[mi], sb + stg + OFF_AL + off);
            }
            #pragma unroll
            for (int ni = 0; ni < NI; ni++) {
                uint32_t off = SWZ64((wn + ni * 8 + brow) * 64 + s * 32 + bkb);
                uint32_t bh[2], bl[2];
                ldmx2(bh, sb + stg + OFF_BH + off);
                ldmx2(bl, sb + stg + OFF_BL + off);
                #pragma unroll
                for (int mi = 0; mi < 2; mi++) {
                    mma_bf16(acc[mi][ni], ah[mi], bh);
                    mma_bf16(acc[mi][ni], ah[mi], bl);
                    mma_bf16(acc[mi][ni], al[mi], bh);
                }
            }
        }
    };

    loadA(0);
    loadB(0, 0);
    storeA(0);
    asm volatile("cp.async.wait_group 0;" ::: "memory");
    __syncthreads();

    uint32_t buf = 0;
    #pragma unroll
    for (int c = 0; c < 8; c++) {
        uint32_t cur = buf * STG, nxt = (buf ^ 1) * STG;
        if (c < 7) {
            loadA((c + 1) * 32);
            loadB(nxt, (c + 1) * 32);
        }
        compute(cur);
        if (c < 7) {
            storeA(nxt);
            asm volatile("cp.async.wait_group 0;" ::: "memory");
            __syncthreads();
        }
        buf ^= 1;
    }

    int g = lane >> 2, tig = lane & 3;
    #pragma unroll
    for (int mi = 0; mi < 2; mi++) {
        int r0 = rowBase + wr + mi * 16 + g;
        int r1 = r0 + 8;
        #pragma unroll
        for (int ni = 0; ni < NI; ni++) {
            int col = wn + ni * 8 + 2 * tig;
            if (col < ncols) {
                if (r0 < nrows)
                    *(__half2*)(Ch + (size_t)r0 * ldC + col) =
                        __floats2half2_rn(acc[mi][ni][0], acc[mi][ni][1]);
                if (r1 < nrows)
                    *(__half2*)(Ch + (size_t)r1 * ldC + col) =
                        __floats2half2_rn(acc[mi][ni][2], acc[mi][ni][3]);
            }
        }
    }
}

// ---------------- edge aggregation: fp16 gather, fp32 accum, MLP=8 ----------
template <int D>
__global__ void edge_agg_kernel(const __half* __restrict__ Yh, __half* __restrict__ Xeh) {
    int warpId = (blockIdx.x * blockDim.x + threadIdx.x) >> 5;
    int lane = threadIdx.x & 31;
    if (warpId >= NE) return;
    int beg = g_eoff[warpId], end = g_eoff[warpId + 1];
    if (D == 256) {
        float f[8];
        #pragma unroll
        for (int q = 0; q < 8; q++) f[q] = 0.f;
        int p = beg;
        for (; p + 7 < end; p += 8) {
            uint4 t[8];
            #pragma unroll
            for (int j = 0; j < 8; j++) {
                int v = g_ev_v[p + j];
                t[j] = ((const uint4*)(Yh + (size_t)v * D))[lane];
            }
            #pragma unroll
            for (int j = 0; j < 8; j++) acc_h4(f, t[j]);
        }
        for (; p + 3 < end; p += 4) {
            uint4 t[4];
            #pragma unroll
            for (int j = 0; j < 4; j++) {
                int v = g_ev_v[p + j];
                t[j] = ((const uint4*)(Yh + (size_t)v * D))[lane];
            }
            #pragma unroll
            for (int j = 0; j < 4; j++) acc_h4(f, t[j]);
        }
        for (; p < end; p++) {
            int v = g_ev_v[p];
            acc_h4(f, ((const uint4*)(Yh + (size_t)v * D))[lane]);
        }
        int cnt = end - beg;
        float s = 1.f / (float)(cnt > 0 ? cnt : 1);
        uint32_t o[4];
        #pragma unroll
        for (int q = 0; q < 4; q++) {
            __half2 h = __floats2half2_rn(f[2 * q] * s, f[2 * q + 1] * s);
            o[q] = *(uint32_t*)&h;
        }
        ((uint4*)(Xeh + (size_t)warpId * D))[lane] = make_uint4(o[0], o[1], o[2], o[3]);
    } else {
        float f0 = 0.f, f1 = 0.f;
        bool act = lane < D / 2;
        int p = beg;
        for (; p + 3 < end; p += 4) {
            int v0 = g_ev_v[p], v1 = g_ev_v[p + 1], v2 = g_ev_v[p + 2], v3 = g_ev_v[p + 3];
            if (act) {
                uint32_t w0 = ((const uint32_t*)(Yh + (size_t)v0 * D))[lane];
                uint32_t w1 = ((const uint32_t*)(Yh + (size_t)v1 * D))[lane];
                uint32_t w2 = ((const uint32_t*)(Yh + (size_t)v2 * D))[lane];
                uint32_t w3 = ((const uint32_t*)(Yh + (size_t)v3 * D))[lane];
                float2 a = __half22float2(*(__half2*)&w0);
                float2 b = __half22float2(*(__half2*)&w1);
                float2 c = __half22float2(*(__half2*)&w2);
                float2 d = __half22float2(*(__half2*)&w3);
                f0 += a.x + b.x + c.x + d.x;
                f1 += a.y + b.y + c.y + d.y;
            }
        }
        for (; p < end; p++) {
            int v = g_ev_v[p];
            if (act) {
                uint32_t t = ((const uint32_t*)(Yh + (size_t)v * D))[lane];
                float2 fv = __half22float2(*(__half2*)&t);
                f0 += fv.x; f1 += fv.y;
            }
        }
        int cnt = end - beg;
        float s = 1.f / (float)(cnt > 0 ? cnt : 1);
        if (act) {
            __half2 h = __floats2half2_rn(f0 * s, f1 * s);
            ((uint32_t*)(Xeh + (size_t)warpId * D))[lane] = *(uint32_t*)&h;
        }
    }
}

// ---------------- node aggregation + residual + L2 norm (+relu) -------------
// OUT_HALF: write fp16 (layer-1 -> Xcur fp16); else fp32.
template <int D, bool RELU, bool OUT_HALF>
__global__ void node_agg_kernel(const __half* __restrict__ Yh, const __half* __restrict__ Xeh,
                                void* __restrict__ Xout) {
    int warpId = (blockIdx.x * blockDim.x + threadIdx.x) >> 5;
    int lane = threadIdx.x & 31;
    if (warpId >= NN) return;
    int beg = g_noff[warpId], end = g_noff[warpId + 1];
    if (D == 256) {
        float f[8];
        {
            uint4 y = ((const uint4*)(Yh + (size_t)warpId * D))[lane];
            uint32_t w[4] = {y.x, y.y, y.z, y.w};
            #pragma unroll
            for (int q = 0; q < 4; q++) {
                float2 fv = __half22float2(*(__half2*)&w[q]);
                f[2 * q] = fv.x; f[2 * q + 1] = fv.y;
            }
        }
        int p = beg;
        for (; p + 3 < end; p += 4) {
            int e0 = g_nv_e[p], e1 = g_nv_e[p + 1], e2 = g_nv_e[p + 2], e3 = g_nv_e[p + 3];
            float a0 = g_nv_att[p], a1 = g_nv_att[p + 1], a2 = g_nv_att[p + 2], a3 = g_nv_att[p + 3];
            uint4 t0 = ((const uint4*)(Xeh + (size_t)e0 * D))[lane];
            uint4 t1 = ((const uint4*)(Xeh + (size_t)e1 * D))[lane];
            uint4 t2 = ((const uint4*)(Xeh + (size_t)e2 * D))[lane];
            uint4 t3 = ((const uint4*)(Xeh + (size_t)e3 * D))[lane];
            fma_h4(f, t0, a0); fma_h4(f, t1, a1); fma_h4(f, t2, a2); fma_h4(f, t3, a3);
        }
        for (; p < end; p++) {
            int e = g_nv_e[p];
            fma_h4(f, ((const uint4*)(Xeh + (size_t)e * D))[lane], g_nv_att[p]);
        }
        float ss = 0.f;
        #pragma unroll
        for (int q = 0; q < 8; q++) ss += f[q] * f[q];
        #pragma unroll
        for (int o = 16; o; o >>= 1) ss += __shfl_xor_sync(0xffffffffu, ss, o);
        float norm = sqrtf(ss);
        float scale = (norm > 0.f) ? (1.f / norm) : 0.f;
        #pragma unroll
        for (int q = 0; q < 8; q++) {
            f[q] *= scale;
            if (RELU) f[q] = fmaxf(f[q], 0.f);
        }
        if (OUT_HALF) {
            uint32_t o[4];
            #pragma unroll
            for (int q = 0; q < 4; q++) {
                __half2 h = __floats2half2_rn(f[2 * q], f[2 * q + 1]);
                o[q] = *(uint32_t*)&h;
            }
            ((uint4*)((__half*)Xout + (size_t)warpId * D))[lane] = make_uint4(o[0], o[1], o[2], o[3]);
        } else {
            float4* o4 = (float4*)((float*)Xout + (size_t)warpId * D);
            o4[2 * lane] = make_float4(f[0], f[1], f[2], f[3]);
            o4[2 * lane + 1] = make_float4(f[4], f[5], f[6], f[7]);
        }
    } else {
        bool act = lane < D / 2;
        float f0 = 0.f, f1 = 0.f;
        if (act) {
            uint32_t y = ((const uint32_t*)(Yh + (size_t)warpId * D))[lane];
            float2 fv = __half22float2(*(__half2*)&y);
            f0 = fv.x; f1 = fv.y;
        }
        int p = beg;
        for (; p + 3 < end; p += 4) {
            int e0 = g_nv_e[p], e1 = g_nv_e[p + 1], e2 = g_nv_e[p + 2], e3 = g_nv_e[p + 3];
            float a0 = g_nv_att[p], a1 = g_nv_att[p + 1], a2 = g_nv_att[p + 2], a3 = g_nv_att[p + 3];
            if (act) {
                uint32_t w0 = ((const uint32_t*)(Xeh + (size_t)e0 * D))[lane];
                uint32_t w1 = ((const uint32_t*)(Xeh + (size_t)e1 * D))[lane];
                uint32_t w2 = ((const uint32_t*)(Xeh + (size_t)e2 * D))[lane];
                uint32_t w3 = ((const uint32_t*)(Xeh + (size_t)e3 * D))[lane];
                float2 a = __half22float2(*(__half2*)&w0);
                float2 b = __half22float2(*(__half2*)&w1);
                float2 c = __half22float2(*(__half2*)&w2);
                float2 d = __half22float2(*(__half2*)&w3);
                f0 = fmaf(a0, a.x, fmaf(a1, b.x, fmaf(a2, c.x, fmaf(a3, d.x, f0))));
                f1 = fmaf(a0, a.y, fmaf(a1, b.y, fmaf(a2, c.y, fmaf(a3, d.y, f1))));
            }
        }
        for (; p < end; p++) {
            int e = g_nv_e[p];
            float att = g_nv_att[p];
            if (act) {
                uint32_t t = ((const uint32_t*)(Xeh + (size_t)e * D))[lane];
                float2 fv = __half22float2(*(__half2*)&t);
                f0 = fmaf(att, fv.x, f0);
                f1 = fmaf(att, fv.y, f1);
            }
        }
        float ss = f0 * f0 + f1 * f1;
        #pragma unroll
        for (int o = 16; o; o >>= 1) ss += __shfl_xor_sync(0xffffffffu, ss, o);
        float norm = sqrtf(ss);
        float scale = (norm > 0.f) ? (1.f / norm) : 0.f;
        f0 *= scale; f1 *= scale;
        if (RELU) { f0 = fmaxf(f0, 0.f); f1 = fmaxf(f1, 0.f); }
        if (act)
            ((float2*)((float*)Xout + (size_t)warpId * D))[lane] = make_float2(f0, f1);
    }
}

// ---------------- launch -----------------------------------------------------
extern "C" void kernel_launch(void* const* d_in, const int* in_sizes, int n_in,
                              void* d_out, int out_size) {
    const float* X    = (const float*)d_in[0];
    const int*   V    = (const int*)d_in[1];
    const int*   E    = (const int*)d_in[2];
    const float* homo = (const float*)d_in[3];
    const float* W1   = (const float*)d_in[4];
    const float* W2   = (const float*)d_in[5];
    const float* Wout = (const float*)d_in[6];
    float* out = (float*)d_out;

    float *pXcur;
    __half *pYh, *pXeh;
    int *pEcnt, *pEoff, *pNcnt, *pNoff, *pPartE, *pPartN;
    __nv_bfloat16 *pW1h, *pW1l, *pW2h, *pW2l, *pW3h, *pW3l;
    cudaGetSymbolAddress((void**)&pXcur, g_Xcur);
    cudaGetSymbolAddress((void**)&pYh, g_Yh);
    cudaGetSymbolAddress((void**)&pXeh, g_Xeh);
    cudaGetSymbolAddress((void**)&pEcnt, g_ecnt);
    cudaGetSymbolAddress((void**)&pEoff, g_eoff);
    cudaGetSymbolAddress((void**)&pNcnt, g_ncnt);
    cudaGetSymbolAddress((void**)&pNoff, g_noff);
    cudaGetSymbolAddress((void**)&pPartE, g_partialE);
    cudaGetSymbolAddress((void**)&pPartN, g_partialN);
    cudaGetSymbolAddress((void**)&pW1h, g_W1h);
    cudaGetSymbolAddress((void**)&pW1l, g_W1l);
    cudaGetSymbolAddress((void**)&pW2h, g_W2h);
    cudaGetSymbolAddress((void**)&pW2l, g_W2l);
    cudaGetSymbolAddress((void**)&pW3h, g_W3h);
    cudaGetSymbolAddress((void**)&pW3l, g_W3l);
    __half* pXcurH = (__half*)pXcur;

    const int SMEM_BIG = 2 * (8192 + 256 * 128);   // 81920
    const int SMEM_SML = 2 * (8192 + 64 * 128);    // 32768

    // One-time resource setup (first call = non-captured correctness run).
    static cudaStream_t sE = nullptr, sN = nullptr;
    static cudaEvent_t evFork = nullptr, evJoinE = nullptr, evJoinN = nullptr;
    if (sE == nullptr) {
        cudaStreamCreateWithFlags(&sE, cudaStreamNonBlocking);
        cudaStreamCreateWithFlags(&sN, cudaStreamNonBlocking);
        cudaEventCreateWithFlags(&evFork, cudaEventDisableTiming);
        cudaEventCreateWithFlags(&evJoinE, cudaEventDisableTiming);
        cudaEventCreateWithFlags(&evJoinN, cudaEventDisableTiming);
        cudaFuncSetAttribute(gemm_mma<256, false>, cudaFuncAttributeMaxDynamicSharedMemorySize, SMEM_BIG);
        cudaFuncSetAttribute(gemm_mma<256, true>, cudaFuncAttributeMaxDynamicSharedMemorySize, SMEM_BIG);
        cudaFuncSetAttribute(gemm_mma<64, false>, cudaFuncAttributeMaxDynamicSharedMemorySize, SMEM_SML);
    }

    int nbE = (NE + 1023) / 1024, nbN = (NN + 1023) / 1024;

    // fork: E-chain and N-chain run concurrently with wsplit + layer-1 GEMM
    cudaEventRecord(evFork, 0);
    cudaStreamWaitEvent(sE, evFork, 0);
    cudaStreamWaitEvent(sN, evFork, 0);

    // E-chain (stream sE): edge CSR only
    zeroE_kernel<<<128, 512, 0, sE>>>();
    histE_kernel<<<(NZ + 255) / 256, 256, 0, sE>>>(E);
    scan_p1<<<nbE, 1024, 0, sE>>>(pEcnt, pEoff, NE, pPartE);
    scan_p2<<<1, 1024, 0, sE>>>(pPartE, nbE);
    scan_p3<<<nbE, 1024, 0, sE>>>(pEoff, NE, pPartE);
    buildE_kernel<<<(NZ + 255) / 256, 256, 0, sE>>>(V, E);
    cudaEventRecord(evJoinE, sE);

    // N-chain (stream sN): node CSR + att weights
    zeroN_kernel<<<128, 512, 0, sN>>>();
    histN_kernel<<<(NZ + 255) / 256, 256, 0, sN>>>(V, E, homo);
    scan_p1<<<nbN, 1024, 0, sN>>>(pNcnt, pNoff, NN, pPartN);
    scan_p2<<<1, 1024, 0, sN>>>(pPartN, nbN);
    scan_p3<<<nbN, 1024, 0, sN>>>(pNoff, NN, pPartN);
    buildN_kernel<<<(NZ + 255) / 256, 256, 0, sN>>>(V, E, homo);
    cudaEventRecord(evJoinN, sN);

    const int gemmGrid = (NN + 63) / 64;
    const int eagBlocks = (NE * 32 + 255) / 256;
    const int nagBlocks = (NN * 32 + 255) / 256;

    // GEMM branch (default stream)
    wsplit_all<<<144, 1024>>>(W1, W2, Wout);
    gemm_mma<256, false><<<gemmGrid, 256, SMEM_BIG>>>(X, pW1h, pW1l, pYh, NN, 256, 256);

    // layer 1: edge agg needs only E-CSR; node agg additionally needs N-CSR
    cudaStreamWaitEvent(0, evJoinE, 0);
    edge_agg_kernel<256><<<eagBlocks, 256>>>(pYh, pXeh);
    cudaStreamWaitEvent(0, evJoinN, 0);
    node_agg_kernel<256, true, true><<<nagBlocks, 256>>>(pYh, pXeh, pXcurH);

    // layer 2 (A fp16) -> Z written directly to out (fp32)
    gemm_mma<256, true><<<gemmGrid, 256, SMEM_BIG>>>(pXcurH, pW2h, pW2l, pYh, NN, 256, 256);
    edge_agg_kernel<256><<<eagBlocks, 256>>>(pYh, pXeh);
    node_agg_kernel<256, true, false><<<nagBlocks, 256>>>(pYh, pXeh, out);

    // layer 3 (A fp32 from out; N padded to 64, C stride 40)
    gemm_mma<64, false><<<gemmGrid, 256, SMEM_SML>>>(out, pW3h, pW3l, pYh, NN, NC, NC);
    edge_agg_kernel<NC><<<eagBlocks, 256>>>(pYh, pXeh);
    node_agg_kernel<NC, false, false><<<nagBlocks, 256>>>(pYh, pXeh, out + (size_t)NN * DH);
}